// round 2
// baseline (speedup 1.0000x reference)
#include <cuda_runtime.h>
#include <cstdint>

#define BB 4
#define HH 1024
#define WW 1920
#define HW (HH * WW)
#define NPIX (BB * HW)
#define ALPHA 100.0f
#define EPSN 1e-7f

// Interleaved accumulator: [pix][4] = {num_r, num_g, num_b, den}, 16B aligned.
__device__ __align__(16) float g_acc[(size_t)NPIX * 4];
// Interleaved rgb2: [B][H][W] x {r,g,b,pad} for single-line bilinear gather.
__device__ __align__(16) float4 g_rgb2i[(size_t)NPIX];

__device__ __forceinline__ void red_add_v4(float* addr, float a, float b, float c, float d) {
    asm volatile("red.global.add.v4.f32 [%0], {%1, %2, %3, %4};"
                 :: "l"(addr), "f"(a), "f"(b), "f"(c), "f"(d) : "memory");
}

// ---- Prologue: planar rgb2 -> interleaved float4 ----
__global__ __launch_bounds__(256)
void interleave_kernel(const float* __restrict__ rgb2) {
    int idx = blockIdx.x * 256 + threadIdx.x;
    if (idx >= NPIX) return;
    int b = idx / HW;
    int rem = idx - b * HW;
    const float* p = rgb2 + (size_t)b * 3 * HW + rem;
    float4 v;
    v.x = __ldcs(p);
    v.y = __ldcs(p + HW);
    v.z = __ldcs(p + 2 * HW);
    v.w = 0.f;
    g_rgb2i[idx] = v;
}

// ---- Main fused kernel: backwarp metric + exp weight + forward splat ----
__global__ __launch_bounds__(192)
void splat_kernel(const float* __restrict__ rgb1,
                  const float* __restrict__ ftgt,
                  const float* __restrict__ f12,
                  float* __restrict__ out) {
    int xp = blockIdx.x * 192 + threadIdx.x;   // pixel-pair index in row: 0..959
    int x  = xp * 2;
    int y  = blockIdx.y;
    int b  = blockIdx.z;
    size_t rem = (size_t)y * WW + x;

    const float* fb = f12 + (size_t)b * 2 * HW + rem;
    float2 fx = __ldcs((const float2*)fb);          // x-flow (src1->src2) for both px
    float2 fy = __ldcs((const float2*)(fb + HW));   // y-flow

    const float* r1 = rgb1 + (size_t)b * 3 * HW + rem;
    float2 c0 = __ldcs((const float2*)r1);
    float2 c1 = __ldcs((const float2*)(r1 + HW));
    float2 c2 = __ldcs((const float2*)(r1 + 2 * HW));

    const float* ftb = ftgt + (size_t)b * 2 * HW + rem;
    float2 gx = __ldcs((const float2*)ftb);
    float2 gy = __ldcs((const float2*)(ftb + HW));

    const float4* r2   = g_rgb2i + (size_t)b * HW;
    float*        accb = g_acc   + (size_t)b * HW * 4;

    float mets[2];
#pragma unroll
    for (int j = 0; j < 2; j++) {
        // ---- bilinear gather of interleaved rgb2 (zeros outside) ----
        float px = (float)(x + j) + (j ? fx.y : fx.x);
        float py = (float)y       + (j ? fy.y : fy.x);
        float x0f = floorf(px), y0f = floorf(py);
        int   x0  = (int)x0f,   y0  = (int)y0f;
        float wx = px - x0f, wy = py - y0f;

        float a0 = 0.f, a1 = 0.f, a2 = 0.f;
#pragma unroll
        for (int cy = 0; cy < 2; cy++) {
#pragma unroll
            for (int cx = 0; cx < 2; cx++) {
                int xi = x0 + cx, yi = y0 + cy;
                if (xi >= 0 && xi < WW && yi >= 0 && yi < HH) {
                    float w = (cx ? wx : 1.f - wx) * (cy ? wy : 1.f - wy);
                    float4 t = __ldg(&r2[yi * WW + xi]);
                    a0 += w * t.x; a1 += w * t.y; a2 += w * t.z;
                }
            }
        }

        float p0 = (j ? c0.y : c0.x);
        float p1 = (j ? c1.y : c1.x);
        float p2 = (j ? c2.y : c2.x);
        float metric = (fabsf(p0 - a0) + fabsf(p1 - a1) + fabsf(p2 - a2)) * (1.f / 3.f);
        mets[j] = metric;

        float em = __expf(fmaxf(-ALPHA * metric, -ALPHA));

        // ---- forward splat (scatter-add) with flow_src1_to_tgt ----
        float qx = (float)(x + j) + (j ? gx.y : gx.x);
        float qy = (float)y       + (j ? gy.y : gy.x);
        float qx0f = floorf(qx), qy0f = floorf(qy);
        int   qx0  = (int)qx0f,  qy0  = (int)qy0f;
        float swx = qx - qx0f, swy = qy - qy0f;

        float v0 = p0 * em, v1 = p1 * em, v2 = p2 * em;
#pragma unroll
        for (int cy = 0; cy < 2; cy++) {
#pragma unroll
            for (int cx = 0; cx < 2; cx++) {
                int xi = qx0 + cx, yi = qy0 + cy;
                if (xi >= 0 && xi < WW && yi >= 0 && yi < HH) {
                    float w = (cx ? swx : 1.f - swx) * (cy ? swy : 1.f - swy);
                    float* p = accb + (size_t)(yi * WW + xi) * 4;
                    red_add_v4(p, v0 * w, v1 * w, v2 * w, em * w);
                }
            }
        }
    }

    // metric output: [B][1][H][W] appended after the 3-channel splat image
    float* mo = out + (size_t)BB * 3 * HW + (size_t)b * HW + rem;
    __stcs((float2*)mo, make_float2(mets[0], mets[1]));
}

// ---- Normalize + re-zero accumulator for the next graph replay ----
__global__ __launch_bounds__(256)
void norm_kernel(float* __restrict__ out) {
    int i = blockIdx.x * 256 + threadIdx.x;   // pair index
    if (i >= NPIX / 2) return;
    int idx = i * 2;
    int b   = idx / HW;
    int rem = idx - b * HW;

    float4* ap = (float4*)(g_acc + (size_t)idx * 4);
    float4 a0 = ap[0];
    float4 a1 = ap[1];
    ap[0] = make_float4(0.f, 0.f, 0.f, 0.f);
    ap[1] = make_float4(0.f, 0.f, 0.f, 0.f);

    float i0 = 1.0f / (a0.w + EPSN);
    float i1 = 1.0f / (a1.w + EPSN);

    float* o = out + (size_t)b * 3 * HW + rem;
    __stcs((float2*)o,            make_float2(a0.x * i0, a1.x * i1));
    __stcs((float2*)(o + HW),     make_float2(a0.y * i0, a1.y * i1));
    __stcs((float2*)(o + 2 * HW), make_float2(a0.z * i0, a1.z * i1));
}

// Tiny 4th launch so ncu's "-s 5" sample lands on splat_kernel next capture.
__global__ void probe_kernel() {}

extern "C" void kernel_launch(void* const* d_in, const int* in_sizes, int n_in,
                              void* d_out, int out_size) {
    const float* rgb1 = (const float*)d_in[0];
    const float* rgb2 = (const float*)d_in[1];
    const float* ftgt = (const float*)d_in[2];  // flow_src1_to_tgt
    const float* f12  = (const float*)d_in[3];  // flow_src1_to_src2
    float* out = (float*)d_out;

    interleave_kernel<<<(NPIX + 255) / 256, 256>>>(rgb2);

    dim3 grid(WW / (192 * 2), HH, BB);   // 5 x 1024 x 4
    splat_kernel<<<grid, 192>>>(rgb1, ftgt, f12, out);

    norm_kernel<<<(NPIX / 2 + 255) / 256, 256>>>(out);

    probe_kernel<<<1, 32>>>();
}